// round 2
// baseline (speedup 1.0000x reference)
#include <cuda_runtime.h>
#include <cstdint>

// Problem shape (fixed by the dataset)
#define T_MAX 16384
#define HID   512
#define GATES 2048   // 4*HID
#define NCTA  64     // persistent CTAs for the recurrence (cooperative launch)
#define NTHR  256

// ---------------------------------------------------------------------------
// Device scratch (no cudaMalloc allowed)
// ---------------------------------------------------------------------------
__device__ float g_hbuf[2][HID];                    // double-buffered h
__device__ float g_xg[(size_t)T_MAX * GATES];       // precomputed input gates
__device__ unsigned g_cnt;                          // grid-barrier arrivals

// ---------------------------------------------------------------------------
// Helpers
// ---------------------------------------------------------------------------
__device__ __forceinline__ void fma2(unsigned long long& a,
                                     unsigned long long w,
                                     unsigned long long h) {
    // two independent fp32 FMAs in one instruction (bit-exact vs fmaf)
    asm("fma.rn.f32x2 %0, %1, %2, %0;" : "+l"(a) : "l"(w), "l"(h));
}
__device__ __forceinline__ void ldcg_2u64(const void* p,
                                          unsigned long long& a,
                                          unsigned long long& b) {
    asm volatile("ld.global.cg.v2.u64 {%0,%1},[%2];"
                 : "=l"(a), "=l"(b) : "l"(p));
}
__device__ __forceinline__ float4 ldcg4(const float4* p) {
    float4 v;
    asm volatile("ld.global.cg.v4.f32 {%0,%1,%2,%3},[%4];"
                 : "=f"(v.x), "=f"(v.y), "=f"(v.z), "=f"(v.w) : "l"(p));
    return v;
}
__device__ __forceinline__ void stcg_f32(float* p, float v) {
    asm volatile("st.global.cg.f32 [%0],%1;" :: "l"(p), "f"(v) : "memory");
}
__device__ __forceinline__ void unpack2(unsigned long long a, float& lo, float& hi) {
    asm("mov.b64 {%0,%1},%2;" : "=f"(lo), "=f"(hi) : "l"(a));
}

// Grid-wide barrier: monotonic counter, release-arrive / acquire-spin.
// target = NCTA * (number of barrier calls so far this launch).
// g_cnt is reset to 0 by gates_kernel before every lstm launch.
__device__ __forceinline__ void grid_bar(unsigned target) {
    __syncthreads();
    if (threadIdx.x == 0) {
        asm volatile("red.release.gpu.global.add.u32 [%0], 1;"
                     :: "l"(&g_cnt) : "memory");
        unsigned v;
        do {
            asm volatile("ld.acquire.gpu.global.u32 %0, [%1];"
                         : "=r"(v) : "l"(&g_cnt) : "memory");
        } while (v < target);
    }
    __syncthreads();
}

// ---------------------------------------------------------------------------
// Kernel A: x_gates precompute (parallel) + barrier-counter reset.
// ---------------------------------------------------------------------------
__global__ void __launch_bounds__(256) gates_kernel(
    const float* __restrict__ x,    // [T,1,32]
    const float* __restrict__ Wih,  // [2048,32]
    const float* __restrict__ bih,  // [2048]
    const float* __restrict__ bhh)  // [2048]
{
    if (blockIdx.x == 0 && threadIdx.x == 0) g_cnt = 0;

    __shared__ __align__(16) float xs[64 * 32];
    const int t0 = blockIdx.x * 64;
    for (int i = threadIdx.x; i < 64 * 32; i += 256)
        xs[i] = x[(size_t)t0 * 32 + i];
    __syncthreads();

    for (int r = threadIdx.x; r < GATES; r += 256) {
        float4 w[8];
#pragma unroll
        for (int i = 0; i < 8; i++)
            w[i] = __ldg((const float4*)(Wih + (size_t)r * 32 + 4 * i));
        const float b = __ldg(bih + r) + __ldg(bhh + r);
#pragma unroll 4
        for (int tt = 0; tt < 64; ++tt) {
            float acc = b;
#pragma unroll
            for (int i = 0; i < 8; i++) {
                float4 xv = *(const float4*)&xs[tt * 32 + 4 * i];
                acc = fmaf(w[i].x, xv.x, acc);
                acc = fmaf(w[i].y, xv.y, acc);
                acc = fmaf(w[i].z, xv.z, acc);
                acc = fmaf(w[i].w, xv.w, acc);
            }
            g_xg[(size_t)(t0 + tt) * GATES + r] = acc;
        }
    }
}

// ---------------------------------------------------------------------------
// Kernel B: persistent sequential LSTM (cooperative launch, 64 CTAs x 256).
// CTA c owns hidden units [8c, 8c+8). Thread (r=tid&31, seg=tid>>5):
//   gate row = (r>>3)*512 + 8c + (r&7); holds W_hh[row][seg*64 .. +64) in
//   registers as 32 packed f32x2. Per step: one grid barrier, packed-FMA
//   matvec against h read straight from L2 (uniform per warp), smem reduce,
//   gates in warp0, publish 8 h values.
// ---------------------------------------------------------------------------
__global__ void __launch_bounds__(NTHR, 1) lstm_kernel(
    const float* __restrict__ Whh,   // [2048,512]
    const float* __restrict__ Wlin,  // [1,512]
    const float* __restrict__ blin,  // [1]
    float* __restrict__ out,         // [1]
    int T)
{
    const int tid = threadIdx.x;
    const int c   = blockIdx.x;
    const int r   = tid & 31;
    const int seg = tid >> 5;
    const int q   = r >> 3;
    const int uu  = r & 7;
    const int grow = q * HID + c * 8 + uu;

    // Weight slice -> registers, packed as f32x2 (32 x u64 = 64 floats)
    unsigned long long w[32];
    {
        const ulonglong2* wp =
            (const ulonglong2*)(Whh + (size_t)grow * HID + seg * 64);
#pragma unroll
        for (int i = 0; i < 16; i++) {
            ulonglong2 v = __ldg(&wp[i]);
            w[2 * i] = v.x; w[2 * i + 1] = v.y;
        }
    }

    __shared__ float part[NTHR];
    float c_state = 0.f;

    // h version 0 = zeros
    if (tid < 8) stcg_f32(&g_hbuf[0][c * 8 + tid], 0.f);

    for (int t = 0; t < T; ++t) {
        // off-critical-path prefetch of this step's input-gate value
        float xgv = 0.f;
        if (seg == 0) xgv = __ldg(&g_xg[(size_t)t * GATES + grow]);

        grid_bar((unsigned)NCTA * (unsigned)(t + 1));  // h_t now visible

        // load h[seg*64 .. +64) as 32 packed f32x2 (uniform within warp)
        unsigned long long h[32];
        {
            const char* hp = (const char*)&g_hbuf[t & 1][seg * 64];
#pragma unroll
            for (int i = 0; i < 16; i++)
                ldcg_2u64(hp + 16 * i, h[2 * i], h[2 * i + 1]);
        }

        unsigned long long a0 = 0ull, a1 = 0ull, a2 = 0ull, a3 = 0ull;
#pragma unroll
        for (int i = 0; i < 32; i += 4) {
            fma2(a0, w[i + 0], h[i + 0]);
            fma2(a1, w[i + 1], h[i + 1]);
            fma2(a2, w[i + 2], h[i + 2]);
            fma2(a3, w[i + 3], h[i + 3]);
        }
        float x0, x1, x2, x3, x4, x5, x6, x7;
        unpack2(a0, x0, x1); unpack2(a1, x2, x3);
        unpack2(a2, x4, x5); unpack2(a3, x6, x7);
        part[tid] = ((x0 + x1) + (x2 + x3)) + ((x4 + x5) + (x6 + x7));
        __syncthreads();

        if (seg == 0) {
            float s = xgv;
            {
                float p0 = part[r]          + part[32 + r];
                float p1 = part[64 + r]     + part[96 + r];
                float p2 = part[128 + r]    + part[160 + r];
                float p3 = part[192 + r]    + part[224 + r];
                s += (p0 + p1) + (p2 + p3);
            }
            // gates: i,f,o sigmoid; g tanh (precise math for accuracy)
            float a;
            if (q == 2) a = tanhf(s);
            else        a = 1.0f / (1.0f + expf(-s));
            float fv = __shfl_sync(0xffffffffu, a, r + 8);
            float gv = __shfl_sync(0xffffffffu, a, r + 16);
            float ov = __shfl_sync(0xffffffffu, a, r + 24);
            if (r < 8) {
                c_state = fmaf(fv, c_state, a * gv);
                float hval = ov * tanhf(c_state);
                stcg_f32(&g_hbuf[(t + 1) & 1][c * 8 + r], hval);
            }
        }
        // no trailing syncthreads: next grid_bar's leading bar.sync orders
        // the part[] WAR hazard.
    }

    // make h_T visible everywhere, then CTA0/warp0 does the projection
    grid_bar((unsigned)NCTA * (unsigned)(T + 1));

    if (c == 0 && seg == 0) {
        const float4* hp4 = (const float4*)&g_hbuf[T & 1][0]; // 128 float4
        float s = 0.f;
#pragma unroll
        for (int i = 0; i < 4; i++) {
            float4 hv = ldcg4(&hp4[i * 32 + r]);
            float4 wl = __ldg((const float4*)Wlin + i * 32 + r);
            s = fmaf(hv.x, wl.x, s);
            s = fmaf(hv.y, wl.y, s);
            s = fmaf(hv.z, wl.z, s);
            s = fmaf(hv.w, wl.w, s);
        }
#pragma unroll
        for (int o = 16; o; o >>= 1) s += __shfl_xor_sync(0xffffffffu, s, o);
        if (r == 0) out[0] = s + __ldg(blin);
    }
}

// ---------------------------------------------------------------------------
// Launch
// ---------------------------------------------------------------------------
extern "C" void kernel_launch(void* const* d_in, const int* in_sizes, int n_in,
                              void* d_out, int out_size)
{
    const float* x    = (const float*)d_in[0];
    const float* Wih  = (const float*)d_in[1];
    const float* Whh  = (const float*)d_in[2];
    const float* bih  = (const float*)d_in[3];
    const float* bhh  = (const float*)d_in[4];
    const float* Wlin = (const float*)d_in[5];
    const float* blin = (const float*)d_in[6];

    int T = in_sizes[0] / 32;
    if (T > T_MAX) T = T_MAX;

    gates_kernel<<<T / 64, 256>>>(x, Wih, bih, bhh);

    // Cooperative launch: driver guarantees all 64 CTAs are co-resident.
    cudaLaunchConfig_t cfg = {};
    cfg.gridDim  = dim3(NCTA, 1, 1);
    cfg.blockDim = dim3(NTHR, 1, 1);
    cfg.dynamicSmemBytes = 0;
    cudaLaunchAttribute attr[1];
    attr[0].id = cudaLaunchAttributeCooperative;
    attr[0].val.cooperative = 1;
    cfg.attrs = attr;
    cfg.numAttrs = 1;
    cudaLaunchKernelEx(&cfg, lstm_kernel,
                       Whh, Wlin, blin, (float*)d_out, T);
}

// round 4
// speedup vs baseline: 1.6305x; 1.6305x over previous
#include <cuda_runtime.h>
#include <cstdint>

// Problem shape (fixed by the dataset)
#define T_MAX 16384
#define HID   512
#define GATES 2048   // 4*HID
#define NCTA  64     // persistent CTAs (cooperative launch)
#define NTHR  256

// ---------------------------------------------------------------------------
// Device scratch (no cudaMalloc allowed)
// ---------------------------------------------------------------------------
// Tagged h exchange: element = (tag<<32) | bits(f32 value). tag = step+1.
// Double-buffered by step parity. gates_kernel zeroes tags each replay.
__device__ unsigned long long g_htag[2][HID];
__device__ float g_xg[(size_t)T_MAX * GATES];   // precomputed input gates

// ---------------------------------------------------------------------------
// Helpers
// ---------------------------------------------------------------------------
__device__ __forceinline__ void fma2(unsigned long long& a,
                                     unsigned long long w,
                                     unsigned long long h) {
    asm("fma.rn.f32x2 %0, %1, %2, %0;" : "+l"(a) : "l"(w), "l"(h));
}
// STRONG relaxed gpu-scope 16B poll load: always L2-coherent, never stale L1.
__device__ __forceinline__ void ld_strong2(const void* p,
                                           unsigned long long& a,
                                           unsigned long long& b) {
    asm volatile("ld.relaxed.gpu.global.v2.u64 {%0,%1},[%2];"
                 : "=l"(a), "=l"(b) : "l"(p) : "memory");
}
// STRONG relaxed gpu-scope 8B publish store.
__device__ __forceinline__ void st_strong(unsigned long long* p,
                                          unsigned long long v) {
    asm volatile("st.relaxed.gpu.global.u64 [%0],%1;"
                 :: "l"(p), "l"(v) : "memory");
}
__device__ __forceinline__ void unpack2(unsigned long long a, float& lo, float& hi) {
    asm("mov.b64 {%0,%1},%2;" : "=f"(lo), "=f"(hi) : "l"(a));
}
__device__ __forceinline__ float fast_exp2(float x) {
    float e; asm("ex2.approx.f32 %0,%1;" : "=f"(e) : "f"(x)); return e;
}
__device__ __forceinline__ float fast_rcp(float x) {
    float r; asm("rcp.approx.f32 %0,%1;" : "=f"(r) : "f"(x)); return r;
}
__device__ __forceinline__ float sigf(float x) {           // ~1e-7 abs err
    x = fminf(fmaxf(x, -30.f), 30.f);
    return fast_rcp(1.f + fast_exp2(-1.4426950408889634f * x));
}
__device__ __forceinline__ float tanhf_fast(float x) {     // 2*sig(2x)-1
    return fmaf(2.f, sigf(2.f * x), -1.f);
}

// ---------------------------------------------------------------------------
// Kernel A: x_gates precompute + tag reset (runs before lstm each replay).
// ---------------------------------------------------------------------------
__global__ void __launch_bounds__(256) gates_kernel(
    const float* __restrict__ x,    // [T,1,32]
    const float* __restrict__ Wih,  // [2048,32]
    const float* __restrict__ bih,  // [2048]
    const float* __restrict__ bhh)  // [2048]
{
    if (blockIdx.x == 0) {
        // zero all tags/values in both h buffers (replay safety)
        for (int i = threadIdx.x; i < 2 * HID; i += 256)
            st_strong(&((unsigned long long*)g_htag)[i], 0ull);
    }

    __shared__ __align__(16) float xs[64 * 32];
    const int t0 = blockIdx.x * 64;
    for (int i = threadIdx.x; i < 64 * 32; i += 256)
        xs[i] = x[(size_t)t0 * 32 + i];
    __syncthreads();

    for (int r = threadIdx.x; r < GATES; r += 256) {
        float4 w[8];
#pragma unroll
        for (int i = 0; i < 8; i++)
            w[i] = __ldg((const float4*)(Wih + (size_t)r * 32 + 4 * i));
        const float b = __ldg(bih + r) + __ldg(bhh + r);
#pragma unroll 4
        for (int tt = 0; tt < 64; ++tt) {
            float acc = b;
#pragma unroll
            for (int i = 0; i < 8; i++) {
                float4 xv = *(const float4*)&xs[tt * 32 + 4 * i];
                acc = fmaf(w[i].x, xv.x, acc);
                acc = fmaf(w[i].y, xv.y, acc);
                acc = fmaf(w[i].z, xv.z, acc);
                acc = fmaf(w[i].w, xv.w, acc);
            }
            g_xg[(size_t)(t0 + tt) * GATES + r] = acc;
        }
    }
}

// ---------------------------------------------------------------------------
// Kernel B: persistent sequential LSTM, 64 CTAs x 256, cooperative.
// Self-validating tagged h with STRONG relaxed ld/st: one L2 handoff/step.
// CTA c owns hidden units [8c,8c+8). Thread (r=tid&31, seg=tid>>5) holds
// W_hh[(r>>3)*512 + 8c + (r&7)][seg*64 .. +64) in regs as 32 packed f32x2.
// ---------------------------------------------------------------------------
__global__ void __launch_bounds__(NTHR, 1) lstm_kernel(
    const float* __restrict__ Whh,   // [2048,512]
    const float* __restrict__ Wlin,  // [1,512]
    const float* __restrict__ blin,  // [1]
    float* __restrict__ out,         // [1]
    int T)
{
    const int tid = threadIdx.x;
    const int c   = blockIdx.x;
    const int r   = tid & 31;
    const int seg = tid >> 5;
    const int q   = r >> 3;
    const int uu  = r & 7;
    const int grow = q * HID + c * 8 + uu;

    // Weight slice -> registers (32 packed f32x2 = 64 floats)
    unsigned long long w[32];
    {
        const ulonglong2* wp =
            (const ulonglong2*)(Whh + (size_t)grow * HID + seg * 64);
#pragma unroll
        for (int i = 0; i < 16; i++) {
            ulonglong2 v = __ldg(&wp[i]);
            w[2 * i] = v.x; w[2 * i + 1] = v.y;
        }
    }

    __shared__ __align__(16) float hs[HID];
    __shared__ float part[NTHR];
    float c_state = 0.f;

    // Publish h_0 = 0 with tag 1 (gates_kernel's reset is stream-ordered first)
    if (tid < 8)
        st_strong(&g_htag[0][c * 8 + tid], 1ull << 32);

    for (int t = 0; t < T; ++t) {
        float xgv = 0.f;
        if (seg == 0) {
            xgv = __ldg(&g_xg[(size_t)t * GATES + grow]);   // overlaps poll

            // ---- poll tagged h: lane r owns pairs (2r + 64k), k=0..7 ----
            const unsigned long long tagv = (unsigned long long)(t + 1);
            const unsigned long long* src = &g_htag[t & 1][0];
            unsigned long long p[16];
            for (;;) {
                bool ok = true;
#pragma unroll
                for (int k = 0; k < 8; k++) {
                    ld_strong2(src + 2 * r + 64 * k, p[2 * k], p[2 * k + 1]);
                    ok &= ((p[2 * k] >> 32) == tagv) &
                          ((p[2 * k + 1] >> 32) == tagv);
                }
                if (__all_sync(0xffffffffu, ok)) break;
            }
            // stage values to smem (float2 per pair)
            float2* hs2 = (float2*)hs;
#pragma unroll
            for (int k = 0; k < 8; k++)
                hs2[r + 32 * k] = make_float2(
                    __uint_as_float((unsigned)p[2 * k]),
                    __uint_as_float((unsigned)p[2 * k + 1]));
        }
        __syncthreads();

        // matvec: 32 packed FMAs per thread, weights in regs, h via LDS
        unsigned long long a0 = 0ull, a1 = 0ull, a2 = 0ull, a3 = 0ull;
        const unsigned long long* hseg = (const unsigned long long*)&hs[seg * 64];
#pragma unroll
        for (int i = 0; i < 32; i += 4) {
            fma2(a0, w[i + 0], hseg[i + 0]);
            fma2(a1, w[i + 1], hseg[i + 1]);
            fma2(a2, w[i + 2], hseg[i + 2]);
            fma2(a3, w[i + 3], hseg[i + 3]);
        }
        float x0, x1, x2, x3, x4, x5, x6, x7;
        unpack2(a0, x0, x1); unpack2(a1, x2, x3);
        unpack2(a2, x4, x5); unpack2(a3, x6, x7);
        part[tid] = ((x0 + x1) + (x2 + x3)) + ((x4 + x5) + (x6 + x7));
        __syncthreads();

        if (seg == 0) {
            float s = xgv;
            {
                float p0 = part[r]       + part[32 + r];
                float p1 = part[64 + r]  + part[96 + r];
                float p2 = part[128 + r] + part[160 + r];
                float p3 = part[192 + r] + part[224 + r];
                s += (p0 + p1) + (p2 + p3);
            }
            float a = (q == 2) ? tanhf_fast(s) : sigf(s);
            float fv = __shfl_sync(0xffffffffu, a, r + 8);
            float gv = __shfl_sync(0xffffffffu, a, r + 16);
            float ov = __shfl_sync(0xffffffffu, a, r + 24);
            if (r < 8) {
                c_state = fmaf(fv, c_state, a * gv);
                float hval = ov * tanhf_fast(c_state);
                unsigned long long pub =
                    ((unsigned long long)(unsigned)(t + 2) << 32) |
                    (unsigned long long)__float_as_uint(hval);
                st_strong(&g_htag[(t + 1) & 1][c * 8 + r], pub);
            }
        }
        // next iteration's leading __syncthreads orders hs/part WAR hazards
    }

    // Final projection (CTA 0, warp 0): poll h_T, dot with W_lin
    if (c == 0 && seg == 0) {
        const unsigned long long tagv = (unsigned long long)(T + 1);
        const unsigned long long* src = &g_htag[T & 1][0];
        unsigned long long p[16];
        for (;;) {
            bool ok = true;
#pragma unroll
            for (int k = 0; k < 8; k++) {
                ld_strong2(src + 2 * r + 64 * k, p[2 * k], p[2 * k + 1]);
                ok &= ((p[2 * k] >> 32) == tagv) &
                      ((p[2 * k + 1] >> 32) == tagv);
            }
            if (__all_sync(0xffffffffu, ok)) break;
        }
        float s = 0.f;
#pragma unroll
        for (int k = 0; k < 8; k++) {
            int e = 2 * r + 64 * k;
            float2 wl = __ldg((const float2*)(Wlin + e));
            s = fmaf(__uint_as_float((unsigned)p[2 * k]),     wl.x, s);
            s = fmaf(__uint_as_float((unsigned)p[2 * k + 1]), wl.y, s);
        }
#pragma unroll
        for (int o = 16; o; o >>= 1) s += __shfl_xor_sync(0xffffffffu, s, o);
        if (r == 0) out[0] = s + __ldg(blin);
    }
}

// ---------------------------------------------------------------------------
// Launch
// ---------------------------------------------------------------------------
extern "C" void kernel_launch(void* const* d_in, const int* in_sizes, int n_in,
                              void* d_out, int out_size)
{
    const float* x    = (const float*)d_in[0];
    const float* Wih  = (const float*)d_in[1];
    const float* Whh  = (const float*)d_in[2];
    const float* bih  = (const float*)d_in[3];
    const float* bhh  = (const float*)d_in[4];
    const float* Wlin = (const float*)d_in[5];
    const float* blin = (const float*)d_in[6];

    int T = in_sizes[0] / 32;
    if (T > T_MAX) T = T_MAX;

    gates_kernel<<<T / 64, 256>>>(x, Wih, bih, bhh);

    cudaLaunchConfig_t cfg = {};
    cfg.gridDim  = dim3(NCTA, 1, 1);
    cfg.blockDim = dim3(NTHR, 1, 1);
    cfg.dynamicSmemBytes = 0;
    cudaLaunchAttribute attr[1];
    attr[0].id = cudaLaunchAttributeCooperative;
    attr[0].val.cooperative = 1;
    cfg.attrs = attr;
    cfg.numAttrs = 1;
    cudaLaunchKernelEx(&cfg, lstm_kernel,
                       Whh, Wlin, blin, (float*)d_out, T);
}

// round 5
// speedup vs baseline: 2.0182x; 1.2378x over previous
#include <cuda_runtime.h>
#include <cstdint>

// Problem shape (fixed by the dataset)
#define T_MAX 16384
#define HID   512
#define GATES 2048   // 4*HID
#define NCTA  64     // persistent CTAs (cooperative launch)
#define NTHR  256

// ---------------------------------------------------------------------------
// Device scratch (no cudaMalloc allowed)
// ---------------------------------------------------------------------------
// Tagged h exchange: element = (tag<<32) | bits(f32 value). tag = step+1.
// Double-buffered by step parity. gates_kernel zeroes tags each replay.
__device__ unsigned long long g_htag[2][HID];
__device__ float g_xg[(size_t)T_MAX * GATES];   // precomputed input gates

// ---------------------------------------------------------------------------
// Helpers
// ---------------------------------------------------------------------------
__device__ __forceinline__ void fma2(unsigned long long& a,
                                     unsigned long long w,
                                     unsigned long long h) {
    asm("fma.rn.f32x2 %0, %1, %2, %0;" : "+l"(a) : "l"(w), "l"(h));
}
// STRONG relaxed gpu-scope 16B poll load: always L2-coherent, never stale L1.
__device__ __forceinline__ void ld_strong2(const void* p,
                                           unsigned long long& a,
                                           unsigned long long& b) {
    asm volatile("ld.relaxed.gpu.global.v2.u64 {%0,%1},[%2];"
                 : "=l"(a), "=l"(b) : "l"(p) : "memory");
}
// STRONG relaxed gpu-scope 8B publish store.
__device__ __forceinline__ void st_strong(unsigned long long* p,
                                          unsigned long long v) {
    asm volatile("st.relaxed.gpu.global.u64 [%0],%1;"
                 :: "l"(p), "l"(v) : "memory");
}
__device__ __forceinline__ void unpack2(unsigned long long a, float& lo, float& hi) {
    asm("mov.b64 {%0,%1},%2;" : "=f"(lo), "=f"(hi) : "l"(a));
}
__device__ __forceinline__ float fast_exp2(float x) {
    float e; asm("ex2.approx.f32 %0,%1;" : "=f"(e) : "f"(x)); return e;
}
__device__ __forceinline__ float fast_rcp(float x) {
    float r; asm("rcp.approx.f32 %0,%1;" : "=f"(r) : "f"(x)); return r;
}
__device__ __forceinline__ float sigf(float x) {           // ~1e-7 abs err
    x = fminf(fmaxf(x, -30.f), 30.f);
    return fast_rcp(1.f + fast_exp2(-1.4426950408889634f * x));
}
__device__ __forceinline__ float tanhf_fast(float x) {     // 2*sig(2x)-1
    return fmaf(2.f, sigf(2.f * x), -1.f);
}

// ---------------------------------------------------------------------------
// Kernel A: x_gates precompute + tag reset (runs before lstm each replay).
// ---------------------------------------------------------------------------
__global__ void __launch_bounds__(256) gates_kernel(
    const float* __restrict__ x,    // [T,1,32]
    const float* __restrict__ Wih,  // [2048,32]
    const float* __restrict__ bih,  // [2048]
    const float* __restrict__ bhh)  // [2048]
{
    if (blockIdx.x == 0) {
        for (int i = threadIdx.x; i < 2 * HID; i += 256)
            st_strong(&((unsigned long long*)g_htag)[i], 0ull);
    }

    __shared__ __align__(16) float xs[64 * 32];
    const int t0 = blockIdx.x * 64;
    for (int i = threadIdx.x; i < 64 * 32; i += 256)
        xs[i] = x[(size_t)t0 * 32 + i];
    __syncthreads();

    for (int r = threadIdx.x; r < GATES; r += 256) {
        float4 w[8];
#pragma unroll
        for (int i = 0; i < 8; i++)
            w[i] = __ldg((const float4*)(Wih + (size_t)r * 32 + 4 * i));
        const float b = __ldg(bih + r) + __ldg(bhh + r);
#pragma unroll 4
        for (int tt = 0; tt < 64; ++tt) {
            float acc = b;
#pragma unroll
            for (int i = 0; i < 8; i++) {
                float4 xv = *(const float4*)&xs[tt * 32 + 4 * i];
                acc = fmaf(w[i].x, xv.x, acc);
                acc = fmaf(w[i].y, xv.y, acc);
                acc = fmaf(w[i].z, xv.z, acc);
                acc = fmaf(w[i].w, xv.w, acc);
            }
            g_xg[(size_t)(t0 + tt) * GATES + r] = acc;
        }
    }
}

// ---------------------------------------------------------------------------
// Kernel B: persistent sequential LSTM, 64 CTAs x 256, cooperative.
// Per-warp segment polling: warp `seg` polls ONLY h[seg*64 .. +64) (one
// strong v2.u64 per lane per round) and starts its FMAs as soon as its
// segment is fresh — no cross-warp wait before compute. xg for step t+1 is
// prefetched a full step ahead (DRAM latency off the critical path).
// ---------------------------------------------------------------------------
__global__ void __launch_bounds__(NTHR, 1) lstm_kernel(
    const float* __restrict__ Whh,   // [2048,512]
    const float* __restrict__ Wlin,  // [1,512]
    const float* __restrict__ blin,  // [1]
    float* __restrict__ out,         // [1]
    int T)
{
    const int tid = threadIdx.x;
    const int c   = blockIdx.x;
    const int r   = tid & 31;
    const int seg = tid >> 5;
    const int q   = r >> 3;
    const int uu  = r & 7;
    const int grow = q * HID + c * 8 + uu;   // gate row for warp0's reduce role

    // Weight slice -> registers (32 packed f32x2 = 64 floats)
    unsigned long long w[32];
    {
        const ulonglong2* wp =
            (const ulonglong2*)(Whh + (size_t)grow * HID + seg * 64);
#pragma unroll
        for (int i = 0; i < 16; i++) {
            ulonglong2 v = __ldg(&wp[i]);
            w[2 * i] = v.x; w[2 * i + 1] = v.y;
        }
    }

    __shared__ __align__(16) float hs[HID];
    __shared__ float part[NTHR];
    float c_state = 0.f;

    // Publish h_0 = 0 with tag 1 (gates_kernel's reset is stream-ordered first)
    if (tid < 8)
        st_strong(&g_htag[0][c * 8 + tid], 1ull << 32);

    // xg prefetch pipeline (warp0 only consumes xg)
    float xg_next = 0.f;
    if (seg == 0) xg_next = __ldg(&g_xg[grow]);   // t = 0

    for (int t = 0; t < T; ++t) {
        float xgv = xg_next;
        if (seg == 0) {
            // issue prefetch for t+1 a full step ahead of its use
            int tn = (t + 1 < T) ? (t + 1) : t;
            xg_next = __ldg(&g_xg[(size_t)tn * GATES + grow]);
        }

        // ---- per-warp poll: lane r owns pair (2r, 2r+1) of segment seg ----
        {
            const unsigned long long tagv = (unsigned long long)(t + 1);
            const unsigned long long* src = &g_htag[t & 1][seg * 64 + 2 * r];
            unsigned long long p0, p1;
            for (;;) {
                ld_strong2(src, p0, p1);
                bool ok = ((p0 >> 32) == tagv) & ((p1 >> 32) == tagv);
                if (__all_sync(0xffffffffu, ok)) break;
            }
            // stage own pair to smem, then warp-local sync
            ((float2*)hs)[seg * 32 + r] = make_float2(
                __uint_as_float((unsigned)p0), __uint_as_float((unsigned)p1));
        }
        __syncwarp();

        // matvec: 32 packed FMAs per thread, weights in regs, h via LDS bcast
        unsigned long long a0 = 0ull, a1 = 0ull, a2 = 0ull, a3 = 0ull;
        const unsigned long long* hseg = (const unsigned long long*)&hs[seg * 64];
#pragma unroll
        for (int i = 0; i < 32; i += 4) {
            fma2(a0, w[i + 0], hseg[i + 0]);
            fma2(a1, w[i + 1], hseg[i + 1]);
            fma2(a2, w[i + 2], hseg[i + 2]);
            fma2(a3, w[i + 3], hseg[i + 3]);
        }
        float x0, x1, x2, x3, x4, x5, x6, x7;
        unpack2(a0, x0, x1); unpack2(a1, x2, x3);
        unpack2(a2, x4, x5); unpack2(a3, x6, x7);
        part[tid] = ((x0 + x1) + (x2 + x3)) + ((x4 + x5) + (x6 + x7));
        __syncthreads();

        if (seg == 0) {
            float s = xgv;
            {
                float p0 = part[r]       + part[32 + r];
                float p1 = part[64 + r]  + part[96 + r];
                float p2 = part[128 + r] + part[160 + r];
                float p3 = part[192 + r] + part[224 + r];
                s += (p0 + p1) + (p2 + p3);
            }
            float a = (q == 2) ? tanhf_fast(s) : sigf(s);
            float fv = __shfl_sync(0xffffffffu, a, r + 8);
            float gv = __shfl_sync(0xffffffffu, a, r + 16);
            float ov = __shfl_sync(0xffffffffu, a, r + 24);
            if (r < 8) {
                c_state = fmaf(fv, c_state, a * gv);
                float hval = ov * tanhf_fast(c_state);
                unsigned long long pub =
                    ((unsigned long long)(unsigned)(t + 2) << 32) |
                    (unsigned long long)__float_as_uint(hval);
                st_strong(&g_htag[(t + 1) & 1][c * 8 + r], pub);
            }
        }
        // order part[] reads (warp0) before next iteration's part[] writes
        __syncthreads();
    }

    // Final projection (CTA 0, warp 0): poll h_T (all segments), dot W_lin
    if (c == 0 && seg == 0) {
        const unsigned long long tagv = (unsigned long long)(T + 1);
        const unsigned long long* src = &g_htag[T & 1][0];
        unsigned long long p[16];
        for (;;) {
            bool ok = true;
#pragma unroll
            for (int k = 0; k < 8; k++) {
                ld_strong2(src + 2 * r + 64 * k, p[2 * k], p[2 * k + 1]);
                ok &= ((p[2 * k] >> 32) == tagv) &
                      ((p[2 * k + 1] >> 32) == tagv);
            }
            if (__all_sync(0xffffffffu, ok)) break;
        }
        float s = 0.f;
#pragma unroll
        for (int k = 0; k < 8; k++) {
            int e = 2 * r + 64 * k;
            float2 wl = __ldg((const float2*)(Wlin + e));
            s = fmaf(__uint_as_float((unsigned)p[2 * k]),     wl.x, s);
            s = fmaf(__uint_as_float((unsigned)p[2 * k + 1]), wl.y, s);
        }
#pragma unroll
        for (int o = 16; o; o >>= 1) s += __shfl_xor_sync(0xffffffffu, s, o);
        if (r == 0) out[0] = s + __ldg(blin);
    }
}

// ---------------------------------------------------------------------------
// Launch
// ---------------------------------------------------------------------------
extern "C" void kernel_launch(void* const* d_in, const int* in_sizes, int n_in,
                              void* d_out, int out_size)
{
    const float* x    = (const float*)d_in[0];
    const float* Wih  = (const float*)d_in[1];
    const float* Whh  = (const float*)d_in[2];
    const float* bih  = (const float*)d_in[3];
    const float* bhh  = (const float*)d_in[4];
    const float* Wlin = (const float*)d_in[5];
    const float* blin = (const float*)d_in[6];

    int T = in_sizes[0] / 32;
    if (T > T_MAX) T = T_MAX;

    gates_kernel<<<T / 64, 256>>>(x, Wih, bih, bhh);

    cudaLaunchConfig_t cfg = {};
    cfg.gridDim  = dim3(NCTA, 1, 1);
    cfg.blockDim = dim3(NTHR, 1, 1);
    cfg.dynamicSmemBytes = 0;
    cudaLaunchAttribute attr[1];
    attr[0].id = cudaLaunchAttributeCooperative;
    attr[0].val.cooperative = 1;
    cfg.attrs = attr;
    cfg.numAttrs = 1;
    cudaLaunchKernelEx(&cfg, lstm_kernel,
                       Whh, Wlin, blin, (float*)d_out, T);
}